// round 1
// baseline (speedup 1.0000x reference)
#include <cuda_runtime.h>
#include <cstdint>

// ---------------- problem constants (fixed by reference) ----------------
#define BB   4
#define NQ   8192
#define DM   256
#define HH   8
#define LL   4
#define KT   2
#define KF   2
#define KK   4
#define DHD  32
#define NVV  5440
#define PCOLS 288   // 64 time + 64 freq + 32 lvl + 128 pt

// level geometry (hardcoded per setup_inputs)
__device__ __constant__ int   c_Wl[LL]   = {64, 32, 16, 8};
__device__ __constant__ int   c_Hl[LL]   = {64, 32, 16, 8};
__device__ __constant__ int   c_lsi[LL]  = {0, 4096, 5120, 5376};
__device__ __constant__ float c_invW[LL] = {1.f/64.f, 1.f/32.f, 1.f/16.f, 1.f/8.f};
__device__ __constant__ float c_invH[LL] = {1.f/64.f, 1.f/32.f, 1.f/16.f, 1.f/8.f};

// ---------------- scratch (static device memory; no allocs) ----------------
__device__ float g_v[BB * NVV * DM];       // projected value  [B, NV, D]
__device__ float g_P[BB * NQ * PCOLS];     // query projections [B*NQ, 288]
__device__ float g_mid[BB * NQ * DM];      // pre-W_o output    [B*NQ, 256]
__device__ float g_Wcat[DM * PCOLS];       // packed projection weights
__device__ float g_bcat[PCOLS];            // packed projection bias

// ---------------- pack the 4 projection weight matrices ----------------
__global__ void pack_kernel(const float* __restrict__ Wt, const float* __restrict__ bt,
                            const float* __restrict__ Wf, const float* __restrict__ bf,
                            const float* __restrict__ Wl, const float* __restrict__ bl,
                            const float* __restrict__ Wp, const float* __restrict__ bp) {
    int i = blockIdx.x * blockDim.x + threadIdx.x;
    if (i < DM * PCOLS) {
        int r = i / PCOLS, c = i % PCOLS;
        float v;
        if      (c < 64)  v = Wt[r * 64  + c];
        else if (c < 128) v = Wf[r * 64  + (c - 64)];
        else if (c < 160) v = Wl[r * 32  + (c - 128)];
        else              v = Wp[r * 128 + (c - 160)];
        g_Wcat[i] = v;
    }
    if (i < PCOLS) {
        float v;
        if      (i < 64)  v = bt[i];
        else if (i < 128) v = bf[i - 64];
        else if (i < 160) v = bl[i - 128];
        else              v = bp[i - 160];
        g_bcat[i] = v;
    }
}

// ---------------- fp32 SGEMM:  C[M,N] = A[M,K] * W[K,N] + bias[N] ----------------
// BM=BN=128, BK=8, 256 threads, 8x8 per thread. Assumes M%128==0, K%8==0.
// N-guards so N=288 works.
__global__ __launch_bounds__(256, 2)
void sgemm_bias(const float* __restrict__ A, const float* __restrict__ W,
                const float* __restrict__ bias, float* __restrict__ C,
                int M, int N, int Kd) {
    __shared__ float As[8][128];
    __shared__ float Ws[8][128];
    const int tid = threadIdx.x;
    const int ty = tid >> 4;          // 0..15
    const int tx = tid & 15;          // 0..15
    const int rowBase = blockIdx.y * 128;
    const int colBase = blockIdx.x * 128;

    float acc[8][8];
#pragma unroll
    for (int i = 0; i < 8; i++)
#pragma unroll
        for (int j = 0; j < 8; j++) acc[i][j] = 0.f;

    const int arow = tid >> 1;          // 0..127
    const int acol = (tid & 1) * 4;     // 0 or 4
    const int wrow = tid >> 5;          // 0..7
    const int wcol = (tid & 31) * 4;    // 0..124

    for (int k0 = 0; k0 < Kd; k0 += 8) {
        float4 av = *reinterpret_cast<const float4*>(&A[(size_t)(rowBase + arow) * Kd + k0 + acol]);
        As[acol + 0][arow] = av.x;
        As[acol + 1][arow] = av.y;
        As[acol + 2][arow] = av.z;
        As[acol + 3][arow] = av.w;

        int gc = colBase + wcol;
        float4 wv = make_float4(0.f, 0.f, 0.f, 0.f);
        if (gc < N) wv = *reinterpret_cast<const float4*>(&W[(size_t)(k0 + wrow) * N + gc]);
        *reinterpret_cast<float4*>(&Ws[wrow][wcol]) = wv;

        __syncthreads();
#pragma unroll
        for (int kk = 0; kk < 8; kk++) {
            float a[8], w[8];
#pragma unroll
            for (int i = 0; i < 8; i++) a[i] = As[kk][ty * 8 + i];
#pragma unroll
            for (int j = 0; j < 8; j++) w[j] = Ws[kk][tx * 8 + j];
#pragma unroll
            for (int i = 0; i < 8; i++)
#pragma unroll
                for (int j = 0; j < 8; j++) acc[i][j] += a[i] * w[j];
        }
        __syncthreads();
    }

#pragma unroll
    for (int i = 0; i < 8; i++) {
        int r = rowBase + ty * 8 + i;
#pragma unroll
        for (int j = 0; j < 8; j++) {
            int c = colBase + tx * 8 + j;
            if (c < N) C[(size_t)r * N + c] = acc[i][j] + bias[c];
        }
    }
}

// ---------------- deformable sampling ----------------
// one warp per (b,q,h); lane = channel d within head (DH=32)
__device__ __forceinline__ float tanh_approx(float x) {
    float r;
    asm("tanh.approx.f32 %0, %1;" : "=f"(r) : "f"(x));
    return r;
}

__global__ __launch_bounds__(256)
void sample_kernel(const float* __restrict__ refp) {
    const int warpInBlk = threadIdx.x >> 5;
    const int lane = threadIdx.x & 31;
    const int gid = blockIdx.x * 8 + warpInBlk;       // 0 .. B*NQ*H-1
    const int h  = gid & (HH - 1);
    const int bq = gid >> 3;                           // b*NQ + q
    const int b  = bq >> 13;                           // NQ = 8192

    const float* __restrict__ P = g_P + (size_t)bq * PCOLS;
    const int hL = h * LL;

    // tanh offsets (broadcast loads; redundant per lane)
    float toff[LL][KT], foff[LL][KF];
#pragma unroll
    for (int l = 0; l < LL; l++) {
#pragma unroll
        for (int kt = 0; kt < KT; kt++) toff[l][kt] = tanh_approx(P[(hL + l) * KT + kt]);
#pragma unroll
        for (int kf = 0; kf < KF; kf++) foff[l][kf] = tanh_approx(P[64 + (hL + l) * KF + kf]);
    }

    // level softmax
    float lw[LL];
    {
        float m = -1e30f;
#pragma unroll
        for (int l = 0; l < LL; l++) { lw[l] = P[128 + hL + l]; m = fmaxf(m, lw[l]); }
        float s = 0.f;
#pragma unroll
        for (int l = 0; l < LL; l++) { lw[l] = __expf(lw[l] - m); s += lw[l]; }
        float inv = __fdividef(1.f, s);
#pragma unroll
        for (int l = 0; l < LL; l++) lw[l] *= inv;
    }

    // point softmax per level
    float pw[LL][KK];
#pragma unroll
    for (int l = 0; l < LL; l++) {
        float m = -1e30f;
#pragma unroll
        for (int k = 0; k < KK; k++) { pw[l][k] = P[160 + (hL + l) * KK + k]; m = fmaxf(m, pw[l][k]); }
        float s = 0.f;
#pragma unroll
        for (int k = 0; k < KK; k++) { pw[l][k] = __expf(pw[l][k] - m); s += pw[l][k]; }
        float inv = __fdividef(1.f, s);
#pragma unroll
        for (int k = 0; k < KK; k++) pw[l][k] *= inv;
    }

    const float* __restrict__ rp = refp + (size_t)bq * (LL * 2);
    const float* __restrict__ vbase = g_v + (size_t)b * NVV * DM + h * DHD + lane;

    float acc = 0.f;
#pragma unroll
    for (int l = 0; l < LL; l++) {
        const int   Wl = c_Wl[l], Hl = c_Hl[l];
        const int   start = c_lsi[l];
        const float rx = rp[l * 2 + 0], ry = rp[l * 2 + 1];
        const float fWl = (float)Wl, fHl = (float)Hl;
#pragma unroll
        for (int k = 0; k < KK; k++) {
            const int kt = k >> 1, kf = k & 1;
            float lx = rx + toff[l][kt] * c_invW[l];
            float ly = ry + foff[l][kf] * c_invH[l];
            lx = fminf(fmaxf(lx, 0.f), 1.f);
            ly = fminf(fmaxf(ly, 0.f), 1.f);
            float x = lx * fWl - 0.5f;
            float y = ly * fHl - 0.5f;
            float x0f = floorf(x), y0f = floorf(y);
            float wx1 = x - x0f, wy1 = y - y0f;
            float wx0 = 1.f - wx1, wy0 = 1.f - wy1;
            int x0 = (int)x0f, y0 = (int)y0f;
            int x1 = x0 + 1,   y1 = y0 + 1;
            const float a = lw[l] * pw[l][k];
            const bool vx0 = (x0 >= 0) & (x0 < Wl);
            const bool vx1 = (x1 >= 0) & (x1 < Wl);
            const bool vy0 = (y0 >= 0) & (y0 < Hl);
            const bool vy1 = (y1 >= 0) & (y1 < Hl);
            if (vx0 & vy0) acc += (a * wx0 * wy0) * vbase[(size_t)(start + y0 * Wl + x0) * DM];
            if (vx1 & vy0) acc += (a * wx1 * wy0) * vbase[(size_t)(start + y0 * Wl + x1) * DM];
            if (vx0 & vy1) acc += (a * wx0 * wy1) * vbase[(size_t)(start + y1 * Wl + x0) * DM];
            if (vx1 & vy1) acc += (a * wx1 * wy1) * vbase[(size_t)(start + y1 * Wl + x1) * DM];
        }
    }

    g_mid[(size_t)bq * DM + h * DHD + lane] = acc;
}

// ---------------- launch ----------------
extern "C" void kernel_launch(void* const* d_in, const int* in_sizes, int n_in,
                              void* d_out, int out_size) {
    const float* query  = (const float*)d_in[0];
    const float* refp   = (const float*)d_in[1];
    const float* value  = (const float*)d_in[2];
    // d_in[3] spatial_shapes, d_in[4] level_start_index : hardcoded
    const float* W_time = (const float*)d_in[5];
    const float* b_time = (const float*)d_in[6];
    const float* W_freq = (const float*)d_in[7];
    const float* b_freq = (const float*)d_in[8];
    const float* W_lvl  = (const float*)d_in[9];
    const float* b_lvl  = (const float*)d_in[10];
    const float* W_pt   = (const float*)d_in[11];
    const float* b_pt   = (const float*)d_in[12];
    const float* W_v    = (const float*)d_in[13];
    const float* b_v    = (const float*)d_in[14];
    const float* W_o    = (const float*)d_in[15];
    const float* b_o    = (const float*)d_in[16];
    float* out = (float*)d_out;

    float *p_v, *p_P, *p_mid, *p_Wcat, *p_bcat;
    cudaGetSymbolAddress((void**)&p_v,    g_v);
    cudaGetSymbolAddress((void**)&p_P,    g_P);
    cudaGetSymbolAddress((void**)&p_mid,  g_mid);
    cudaGetSymbolAddress((void**)&p_Wcat, g_Wcat);
    cudaGetSymbolAddress((void**)&p_bcat, g_bcat);

    // 1. pack projection weights
    pack_kernel<<<(DM * PCOLS + 255) / 256, 256>>>(W_time, b_time, W_freq, b_freq,
                                                   W_lvl, b_lvl, W_pt, b_pt);

    // 2. value projection: [B*NV, 256] x [256, 256]
    {
        dim3 grid(DM / 128, (BB * NVV) / 128);
        sgemm_bias<<<grid, 256>>>(value, W_v, b_v, p_v, BB * NVV, DM, DM);
    }

    // 3. query projections: [B*NQ, 288] = query x Wcat
    {
        dim3 grid((PCOLS + 127) / 128, (BB * NQ) / 128);
        sgemm_bias<<<grid, 256>>>(query, p_Wcat, p_bcat, p_P, BB * NQ, PCOLS, DM);
    }

    // 4. deformable sampling: one warp per (b,q,h)
    {
        int totalWarps = BB * NQ * HH;          // 262144
        sample_kernel<<<totalWarps / 8, 256>>>(refp);
    }

    // 5. output projection: [B*NQ, 256] x [256, 256] -> d_out
    {
        dim3 grid(DM / 128, (BB * NQ) / 128);
        sgemm_bias<<<grid, 256>>>(p_mid, W_o, b_o, out, BB * NQ, DM, DM);
    }
}

// round 3
// speedup vs baseline: 2.1542x; 2.1542x over previous
#include <cuda_runtime.h>
#include <cuda_bf16.h>
#include <cstdint>

// ---------------- problem constants ----------------
#define BB   4
#define NQ   8192
#define DM   256
#define HH   8
#define LL   4
#define DHD  32
#define NVV  5440
#define PCOLS 288
#define K3   768          // split-K: [A_hi | A_lo | A_hi] x [W_hi ; W_hi ; W_lo]
#define NITER 24          // 768 / 32
#define BK   32

__device__ __constant__ int   c_Wl[LL]   = {64, 32, 16, 8};
__device__ __constant__ int   c_lsi[LL]  = {0, 4096, 5120, 5376};
__device__ __constant__ float c_inv[LL]  = {1.f/64.f, 1.f/32.f, 1.f/16.f, 1.f/8.f};

// ---------------- static device scratch ----------------
__device__ __nv_bfloat16 g_Abig[32768 * K3];   // split-bf16 A (reused by all 3 GEMMs)
__device__ __nv_bfloat16 g_WbigT[384 * K3];    // split-bf16 W^T (N-major), padded to 384 rows
__device__ float g_v[BB * NVV * DM];
__device__ float g_P[BB * NQ * PCOLS];
__device__ float g_Wcat[DM * PCOLS];
__device__ float g_bcat[PCOLS];

// ---------------- helpers ----------------
__device__ __forceinline__ uint32_t smem_u32(const void* p) {
    uint32_t a;
    asm("{ .reg .u64 t; cvta.to.shared.u64 t, %1; cvt.u32.u64 %0, t; }" : "=r"(a) : "l"(p));
    return a;
}
__device__ __forceinline__ void cpa16(uint32_t s, const void* g) {
    asm volatile("cp.async.cg.shared.global [%0], [%1], 16;" :: "r"(s), "l"(g));
}
#define CPA_COMMIT() asm volatile("cp.async.commit_group;" ::: "memory")
#define SWZ64(x) ((x) ^ (((x) >> 3) & 0x30))

__device__ __forceinline__ void ldsm4(uint32_t& r0, uint32_t& r1, uint32_t& r2, uint32_t& r3,
                                      uint32_t addr) {
    asm volatile("ldmatrix.sync.aligned.m8n8.x4.shared.b16 {%0,%1,%2,%3}, [%4];"
                 : "=r"(r0), "=r"(r1), "=r"(r2), "=r"(r3) : "r"(addr));
}
__device__ __forceinline__ void mma16816(float* c, uint32_t a0, uint32_t a1, uint32_t a2,
                                         uint32_t a3, uint32_t b0, uint32_t b1) {
    asm volatile("mma.sync.aligned.m16n8k16.row.col.f32.bf16.bf16.f32 "
                 "{%0,%1,%2,%3}, {%4,%5,%6,%7}, {%8,%9}, {%0,%1,%2,%3};"
                 : "+f"(c[0]), "+f"(c[1]), "+f"(c[2]), "+f"(c[3])
                 : "r"(a0), "r"(a1), "r"(a2), "r"(a3), "r"(b0), "r"(b1));
}

// ---------------- pack projection weights [256 x 288] ----------------
__global__ void pack_kernel(const float* __restrict__ Wt, const float* __restrict__ bt,
                            const float* __restrict__ Wf, const float* __restrict__ bf,
                            const float* __restrict__ Wl, const float* __restrict__ bl,
                            const float* __restrict__ Wp, const float* __restrict__ bp) {
    int i = blockIdx.x * blockDim.x + threadIdx.x;
    if (i < DM * PCOLS) {
        int r = i / PCOLS, c = i % PCOLS;
        float v;
        if      (c < 64)  v = Wt[r * 64  + c];
        else if (c < 128) v = Wf[r * 64  + (c - 64)];
        else if (c < 160) v = Wl[r * 32  + (c - 128)];
        else              v = Wp[r * 128 + (c - 160)];
        g_Wcat[i] = v;
    }
    if (i < PCOLS) {
        float v;
        if      (i < 64)  v = bt[i];
        else if (i < 128) v = bf[i - 64];
        else if (i < 160) v = bl[i - 128];
        else              v = bp[i - 160];
        g_bcat[i] = v;
    }
}

// ---------------- fp32 -> split-bf16 conversions ----------------
__global__ void convA_kernel(const float* __restrict__ A, int total) {
    int i = blockIdx.x * blockDim.x + threadIdx.x;
    if (i >= total) return;
    int r = i >> 8, c = i & 255;
    float v = A[i];
    __nv_bfloat16 hi = __float2bfloat16(v);
    __nv_bfloat16 lo = __float2bfloat16(v - __bfloat162float(hi));
    size_t base = (size_t)r * K3 + c;
    g_Abig[base]       = hi;
    g_Abig[base + 256] = lo;
    g_Abig[base + 512] = hi;
}

// W is [256 x N] row-major; produce W^T split [384 x 768] (rows n>=N zero)
__global__ void convW_kernel(const float* __restrict__ W, int N) {
    int i = blockIdx.x * blockDim.x + threadIdx.x;
    if (i >= 384 * 256) return;
    int n = i >> 8, k = i & 255;
    float v = (n < N) ? W[k * N + n] : 0.f;
    __nv_bfloat16 hi = __float2bfloat16(v);
    __nv_bfloat16 lo = __float2bfloat16(v - __bfloat162float(hi));
    size_t base = (size_t)n * K3 + k;
    g_WbigT[base]       = hi;
    g_WbigT[base + 256] = hi;
    g_WbigT[base + 512] = lo;
}

// ---------------- bf16 mma.sync GEMM: C[M,N] = Abig[M,768] * WbigT^T + bias ----------------
// 128x128 tile, BK=32, 3-stage cp.async pipeline (48 KB smem), 8 warps (4M x 2N),
// warp tile 32x64, m16n8k16 HMMA, fp32 accumulate.
__global__ __launch_bounds__(256, 2)
void gemm_mma(const __nv_bfloat16* __restrict__ A,
              const float* __restrict__ bias, float* __restrict__ C,
              int M, int N) {
    extern __shared__ char smem[];                  // 3 * 16384
    const uint32_t sb = smem_u32(smem);
    const int tid = threadIdx.x, wid = tid >> 5, lane = tid & 31;
    const int wm = wid >> 1, wn = wid & 1;
    const int rowBase = blockIdx.y * 128, colBase = blockIdx.x * 128;

    const __nv_bfloat16* __restrict__ Bt = g_WbigT;

    // per-stage: A tile [128][32] at +0 (8KB), B tile [128][32] at +8192
    auto load = [&](int j, int s) {
        uint32_t abase = sb + s * 16384;
        uint32_t bbase = abase + 8192;
        const __nv_bfloat16* ga = A  + (size_t)rowBase * K3 + j * BK;
        const __nv_bfloat16* gb = Bt + (size_t)colBase * K3 + j * BK;
#pragma unroll
        for (int it = 0; it < 2; it++) {
            int id = tid + it * 256;                // 0..511
            int r = id >> 2, c4 = (id & 3) * 16;    // byte col
            uint32_t sw = SWZ64(r * 64 + c4);
            cpa16(abase + sw, (const char*)(ga + (size_t)r * K3) + c4);
            cpa16(bbase + sw, (const char*)(gb + (size_t)r * K3) + c4);
        }
        CPA_COMMIT();
    };

    float acc[2][8][4];
#pragma unroll
    for (int mi = 0; mi < 2; mi++)
#pragma unroll
        for (int ni = 0; ni < 8; ni++)
#pragma unroll
            for (int q = 0; q < 4; q++) acc[mi][ni][q] = 0.f;

    load(0, 0); load(1, 1);

    // precomputed ldmatrix lane addressing (within-tile byte offsets)
    const int aRow = (lane & 15);                   // + mBase
    const int aK   = (lane >> 4) << 3;              // 0 or 8
    const int bRow = (lane & 7) + ((lane >> 4) << 3);
    const int bK   = ((lane >> 3) & 1) << 3;

    for (int i = 0; i < NITER; i++) {
        asm volatile("cp.async.wait_group 1;" ::: "memory");
        __syncthreads();
        if (i + 2 < NITER) load(i + 2, (i + 2) % 3);
        else CPA_COMMIT();                          // keep group count uniform

        uint32_t abase = sb + (i % 3) * 16384;
        uint32_t bbase = abase + 8192;
#pragma unroll
        for (int kk = 0; kk < BK; kk += 16) {
            uint32_t a[2][4];
#pragma unroll
            for (int mi = 0; mi < 2; mi++) {
                int row = wm * 32 + mi * 16 + aRow;
                int kb  = (kk + aK) * 2;
                ldsm4(a[mi][0], a[mi][1], a[mi][2], a[mi][3],
                      abase + SWZ64(row * 64 + kb));
            }
            uint32_t b[4][4];
#pragma unroll
            for (int ng = 0; ng < 4; ng++) {
                int row = wn * 64 + ng * 16 + bRow;
                int kb  = (kk + bK) * 2;
                ldsm4(b[ng][0], b[ng][1], b[ng][2], b[ng][3],
                      bbase + SWZ64(row * 64 + kb));
            }
#pragma unroll
            for (int mi = 0; mi < 2; mi++)
#pragma unroll
                for (int ni = 0; ni < 8; ni++) {
                    int ng = ni >> 1, half = ni & 1;
                    mma16816(acc[mi][ni], a[mi][0], a[mi][1], a[mi][2], a[mi][3],
                             b[ng][half * 2], b[ng][half * 2 + 1]);
                }
        }
        __syncthreads();
    }

    // epilogue
    const int g = lane >> 2, tig = lane & 3;
#pragma unroll
    for (int mi = 0; mi < 2; mi++) {
        int r0 = rowBase + wm * 32 + mi * 16 + g;
        int r1 = r0 + 8;
#pragma unroll
        for (int ni = 0; ni < 8; ni++) {
            int c = colBase + wn * 64 + ni * 8 + tig * 2;
            if (c < N) {
                float bx = __ldg(&bias[c]), by = __ldg(&bias[c + 1]);
                float2 v0 = make_float2(acc[mi][ni][0] + bx, acc[mi][ni][1] + by);
                float2 v1 = make_float2(acc[mi][ni][2] + bx, acc[mi][ni][3] + by);
                *reinterpret_cast<float2*>(C + (size_t)r0 * N + c) = v0;
                *reinterpret_cast<float2*>(C + (size_t)r1 * N + c) = v1;
            }
        }
    }
}

// ---------------- deformable sampling ----------------
__device__ __forceinline__ float tanh_approx(float x) {
    float r;
    asm("tanh.approx.f32 %0, %1;" : "=f"(r) : "f"(x));
    return r;
}

// one warp per (b,q,h); lanes 0..15 precompute the 16 samples' taps; all 32 gather
__global__ __launch_bounds__(256)
void sample_kernel(const float* __restrict__ refp) {
    __shared__ int   s_idx[8][64];
    __shared__ float s_w[8][64];

    const int warp = threadIdx.x >> 5;
    const int lane = threadIdx.x & 31;
    const int gid = blockIdx.x * 8 + warp;            // 0..B*NQ*H-1
    const int h  = gid & (HH - 1);
    const int bq = gid >> 3;
    const int b  = bq >> 13;                          // NQ=8192

    const float* __restrict__ P = g_P + (size_t)bq * PCOLS;
    const int hL = h * LL;

    if (lane < 16) {
        const int l  = lane >> 2, k = lane & 3;
        const int kt = k >> 1,    kf = k & 1;
        const float t = tanh_approx(P[(hL + l) * 2 + kt]);
        const float f = tanh_approx(P[64 + (hL + l) * 2 + kf]);

        // level softmax (pick level l)
        float e0 = P[128 + hL + 0], e1 = P[128 + hL + 1];
        float e2 = P[128 + hL + 2], e3 = P[128 + hL + 3];
        float mx = fmaxf(fmaxf(e0, e1), fmaxf(e2, e3));
        float x0e = __expf(e0 - mx), x1e = __expf(e1 - mx);
        float x2e = __expf(e2 - mx), x3e = __expf(e3 - mx);
        float lsum = x0e + x1e + x2e + x3e;
        float lwv = (l == 0 ? x0e : l == 1 ? x1e : l == 2 ? x2e : x3e);

        // point softmax (pick point k)
        const float* pp = P + 160 + (hL + l) * 4;
        float p0 = pp[0], p1 = pp[1], p2 = pp[2], p3 = pp[3];
        float pm = fmaxf(fmaxf(p0, p1), fmaxf(p2, p3));
        float q0 = __expf(p0 - pm), q1 = __expf(p1 - pm);
        float q2 = __expf(p2 - pm), q3 = __expf(p3 - pm);
        float psum = q0 + q1 + q2 + q3;
        float pwv = (k == 0 ? q0 : k == 1 ? q1 : k == 2 ? q2 : q3);

        const float a = __fdividef(lwv * pwv, lsum * psum);

        const float* rp = refp + (size_t)bq * (LL * 2);
        const int   Wl = c_Wl[l];
        const int   start = c_lsi[l];
        const float fWl = (float)Wl;
        float lx = rp[l * 2 + 0] + t * c_inv[l];
        float ly = rp[l * 2 + 1] + f * c_inv[l];
        lx = fminf(fmaxf(lx, 0.f), 1.f);
        ly = fminf(fmaxf(ly, 0.f), 1.f);
        float x = lx * fWl - 0.5f;
        float y = ly * fWl - 0.5f;       // Hl == Wl for all levels
        float x0f = floorf(x), y0f = floorf(y);
        float wx1 = x - x0f, wy1 = y - y0f;
        float wx0 = 1.f - wx1, wy0 = 1.f - wy1;
        int x0 = (int)x0f, y0 = (int)y0f;

#pragma unroll
        for (int j = 0; j < 4; j++) {
            int xi = x0 + (j & 1), yi = y0 + (j >> 1);
            float w = a * ((j & 1) ? wx1 : wx0) * ((j >> 1) ? wy1 : wy0);
            bool valid = (xi >= 0) & (xi < Wl) & (yi >= 0) & (yi < Wl);
            int xc = min(max(xi, 0), Wl - 1);
            int yc = min(max(yi, 0), Wl - 1);
            s_idx[warp][lane * 4 + j] = start + yc * Wl + xc;
            s_w[warp][lane * 4 + j]   = valid ? w : 0.f;
        }
    }
    __syncwarp();

    const float* __restrict__ vb = g_v + (size_t)b * NVV * DM + h * DHD + lane;
    float acc = 0.f;
#pragma unroll 16
    for (int t = 0; t < 64; t++) {
        acc += s_w[warp][t] * vb[(size_t)s_idx[warp][t] * DM];
    }

    // write directly as split-bf16 into Abig for the output GEMM
    const int col = h * DHD + lane;
    size_t base = (size_t)bq * K3 + col;
    __nv_bfloat16 hi = __float2bfloat16(acc);
    __nv_bfloat16 lo = __float2bfloat16(acc - __bfloat162float(hi));
    g_Abig[base]       = hi;
    g_Abig[base + 256] = lo;
    g_Abig[base + 512] = hi;
}

// ---------------- launch ----------------
extern "C" void kernel_launch(void* const* d_in, const int* in_sizes, int n_in,
                              void* d_out, int out_size) {
    const float* query  = (const float*)d_in[0];
    const float* refp   = (const float*)d_in[1];
    const float* value  = (const float*)d_in[2];
    const float* W_time = (const float*)d_in[5];
    const float* b_time = (const float*)d_in[6];
    const float* W_freq = (const float*)d_in[7];
    const float* b_freq = (const float*)d_in[8];
    const float* W_lvl  = (const float*)d_in[9];
    const float* b_lvl  = (const float*)d_in[10];
    const float* W_pt   = (const float*)d_in[11];
    const float* b_pt   = (const float*)d_in[12];
    const float* W_v    = (const float*)d_in[13];
    const float* b_v    = (const float*)d_in[14];
    const float* W_o    = (const float*)d_in[15];
    const float* b_o    = (const float*)d_in[16];
    float* out = (float*)d_out;

    float *p_v, *p_P, *p_Wcat, *p_bcat;
    __nv_bfloat16* p_Abig;
    cudaGetSymbolAddress((void**)&p_v,    g_v);
    cudaGetSymbolAddress((void**)&p_P,    g_P);
    cudaGetSymbolAddress((void**)&p_Wcat, g_Wcat);
    cudaGetSymbolAddress((void**)&p_bcat, g_bcat);
    cudaGetSymbolAddress((void**)&p_Abig, g_Abig);

    const int GEMM_SMEM = 3 * 16384;   // 48 KB — within default dynamic smem limit

    // 1) pack Wcat (fp32)
    pack_kernel<<<(DM * PCOLS + 255) / 256, 256>>>(W_time, b_time, W_freq, b_freq,
                                                   W_lvl, b_lvl, W_pt, b_pt);

    // 2) value GEMM: g_v = value @ W_v + b_v   [21760 x 256]
    convW_kernel<<<(384 * 256 + 255) / 256, 256>>>(W_v, DM);
    convA_kernel<<<(BB * NVV * DM + 255) / 256, 256>>>(value, BB * NVV * DM);
    {
        dim3 grid(2, (BB * NVV) / 128);
        gemm_mma<<<grid, 256, GEMM_SMEM>>>(p_Abig, b_v, p_v, BB * NVV, DM);
    }

    // 3) query projections: g_P = query @ Wcat + bcat   [32768 x 288]
    convW_kernel<<<(384 * 256 + 255) / 256, 256>>>(p_Wcat, PCOLS);
    convA_kernel<<<(BB * NQ * DM + 255) / 256, 256>>>(query, BB * NQ * DM);
    {
        dim3 grid(3, (BB * NQ) / 128);
        gemm_mma<<<grid, 256, GEMM_SMEM>>>(p_Abig, p_bcat, p_P, BB * NQ, PCOLS);
    }

    // 4) deformable sampling -> writes split-bf16 mid directly into Abig
    sample_kernel<<<(BB * NQ * HH) / 8, 256>>>(refp);

    // 5) output GEMM: out = mid @ W_o + b_o   [32768 x 256]
    convW_kernel<<<(384 * 256 + 255) / 256, 256>>>(W_o, DM);
    {
        dim3 grid(2, (BB * NQ) / 128);
        gemm_mma<<<grid, 256, GEMM_SMEM>>>(p_Abig, b_o, out, BB * NQ, DM);
    }
}